// round 3
// baseline (speedup 1.0000x reference)
#include <cuda_runtime.h>

// Fused causal single-head attention, fp32.
//   B=16384 batches, T=32 context, D=64 ndim, H=64 head.
//   out[b] = softmax_causal( 8 * (x Wq)(x Wk)^T ) @ (x Wv)
// Algebra: S = x (8*Wq Wk^T) x^T with M = 8*Wq*Wk^T precomputed (tiny kernel),
//          out = (p @ x) @ Wv.
// All heavy math in packed fma.rn.f32x2 (FFMA2, sm_103a only).

constexpr int T = 32;     // context
constexpr int D = 64;     // ndim
constexpr int H = 64;     // head size
constexpr int XS = 68;    // padded smem row stride (floats); 272B = 17*16 keeps 16B align
constexpr int WARPS_PER_CTA = 4;
constexpr int THREADS = 128;

__device__ float g_M[D * D];   // M = 8 * Wq * Wk^T  (device scratch, no allocation)

typedef unsigned long long u64;

__device__ __forceinline__ u64 fma2(u64 a, u64 b, u64 c) {
    u64 d;
    asm("fma.rn.f32x2 %0, %1, %2, %3;" : "=l"(d) : "l"(a), "l"(b), "l"(c));
    return d;
}
__device__ __forceinline__ u64 pack2(float lo, float hi) {
    u64 r;
    asm("mov.b64 %0, {%1, %2};" : "=l"(r) : "f"(lo), "f"(hi));
    return r;
}
__device__ __forceinline__ float2 unpack2(u64 v) {
    float2 f;
    asm("mov.b64 {%0, %1}, %2;" : "=f"(f.x), "=f"(f.y) : "l"(v));
    return f;
}

// ---------------------------------------------------------------------------
// Pre-kernel: M[i][j] = 8 * sum_h Wq[i][h] * Wk[j][h]   (64x64, trivial cost)
// ---------------------------------------------------------------------------
__global__ void compute_M_kernel(const float* __restrict__ Wk,
                                 const float* __restrict__ Wq) {
    __shared__ float sq[D * H];
    __shared__ float sk[D * H];
    int tid = threadIdx.x;
    for (int i = tid; i < (D * H) / 4; i += blockDim.x) {
        ((float4*)sq)[i] = ((const float4*)Wq)[i];
        ((float4*)sk)[i] = ((const float4*)Wk)[i];
    }
    __syncthreads();
    for (int e = tid; e < D * D; e += blockDim.x) {
        int i = e >> 6;
        int j = e & 63;
        float acc = 0.f;
#pragma unroll
        for (int h = 0; h < H; h++) acc += sq[i * H + h] * sk[j * H + h];
        g_M[e] = 8.0f * acc;   // fold sqrt(head_size)=8 scale into M
    }
}

// ---------------------------------------------------------------------------
// Main kernel: 1 warp per batch, lane t owns query row t.
// smem: Ms[64][64], Wvs[64][64] shared by CTA; per-warp x tile [32][68].
// ---------------------------------------------------------------------------
__global__ void __launch_bounds__(THREADS, 3)
head_kernel(const float* __restrict__ x,
            const float* __restrict__ Wv,
            float* __restrict__ out,
            int nbatch) {
    extern __shared__ float sm[];
    float* Ms  = sm;                // D*D
    float* Wvs = sm + D * D;        // D*H
    const int tid  = threadIdx.x;
    const int warp = tid >> 5;
    const int lane = tid & 31;
    float* xs = sm + 2 * D * H + warp * (T * XS);

    const int batch = blockIdx.x * WARPS_PER_CTA + warp;
    const bool active = (batch < nbatch);
    const float* xb = x + (size_t)batch * (T * D);
    float* ob = out + (size_t)batch * (T * H);

    // Per-warp x tile load FIRST (starts the long-latency LDG early; its STS
    // target is disjoint from the weight region, so no barrier needed yet).
    if (active) {
        for (int i = lane; i < (T * D) / 4; i += 32) {
            float4 v = ((const float4*)xb)[i];
            int r = i >> 4;
            int c = (i & 15) << 2;
            *(float4*)(xs + r * XS + c) = v;
        }
    }

    // Cooperative weight load (broadcast-reused by all warps)
    for (int i = tid; i < (D * D) / 4; i += THREADS)
        ((float4*)Ms)[i] = ((const float4*)g_M)[i];
    for (int i = tid; i < (D * H) / 4; i += THREADS)
        ((float4*)Wvs)[i] = ((const float4*)Wv)[i];
    __syncthreads();

    if (!active) return;

    // ---- Phase 1: y_t = x_t @ M  (lane t), packed over H pairs ----
    // x scalars come from the lane's own row via conflict-free LDS.128
    // (addr = 272*t + 16*c -> 16t mod 128 distinct within each 8-lane phase).
    u64 y2[32];
#pragma unroll
    for (int k = 0; k < 32; k++) y2[k] = 0ULL;
    {
        const float4* xrow4 = (const float4*)(xs + lane * XS);
#pragma unroll 1
        for (int dc = 0; dc < 16; dc++) {
            float4 xv4 = xrow4[dc];
#pragma unroll
            for (int j = 0; j < 4; j++) {
                float xv = (j == 0) ? xv4.x : (j == 1) ? xv4.y : (j == 2) ? xv4.z : xv4.w;
                u64 x2 = pack2(xv, xv);
                const ulonglong2* Mr = (const ulonglong2*)(Ms + ((4 * dc + j) << 6));
#pragma unroll
                for (int k = 0; k < 16; k++) {
                    ulonglong2 mv = Mr[k];
                    y2[2 * k]     = fma2(x2, mv.x, y2[2 * k]);
                    y2[2 * k + 1] = fma2(x2, mv.y, y2[2 * k + 1]);
                }
            }
        }
    }

    // ---- Phase 2: logit[s] = y_t . x_s  (x rows broadcast, conflict-free) ----
    // 4 independent accumulator chains so FMA2 issue never waits on RAW.
    float p[T];
#pragma unroll 1
    for (int s = 0; s < T; s++) {
        const ulonglong2* xr = (const ulonglong2*)(xs + s * XS);
        u64 a0 = 0ULL, a1 = 0ULL, a2 = 0ULL, a3 = 0ULL;
#pragma unroll
        for (int k = 0; k < 8; k++) {
            ulonglong2 xv0 = xr[2 * k];
            ulonglong2 xv1 = xr[2 * k + 1];
            a0 = fma2(y2[4 * k],     xv0.x, a0);
            a1 = fma2(y2[4 * k + 1], xv0.y, a1);
            a2 = fma2(y2[4 * k + 2], xv1.x, a2);
            a3 = fma2(y2[4 * k + 3], xv1.y, a3);
        }
        float2 f0 = unpack2(a0);
        float2 f1 = unpack2(a1);
        float2 f2 = unpack2(a2);
        float2 f3 = unpack2(a3);
        p[s] = ((f0.x + f0.y) + (f1.x + f1.y)) + ((f2.x + f2.y) + (f3.x + f3.y));
    }

    // ---- Phase 3: causal softmax (scale already folded into M) ----
    float mx = -1e30f;
#pragma unroll
    for (int s = 0; s < T; s++) {
        p[s] = (s <= lane) ? p[s] : -1e30f;
        mx = fmaxf(mx, p[s]);
    }
    float sum = 0.f;
#pragma unroll
    for (int s = 0; s < T; s++) {
        p[s] = __expf(p[s] - mx);   // masked entries underflow to exactly 0
        sum += p[s];
    }
    float inv = 1.0f / sum;
#pragma unroll
    for (int s = 0; s < T; s++) p[s] *= inv;

    // ---- Phase 4: z_t = sum_s p[s] * x_s   (packed over D pairs) ----
    u64 z2[32];
#pragma unroll
    for (int k = 0; k < 32; k++) z2[k] = 0ULL;
#pragma unroll 1
    for (int s = 0; s < T; s++) {
        u64 p2 = pack2(p[s], p[s]);
        const ulonglong2* xr = (const ulonglong2*)(xs + s * XS);
#pragma unroll
        for (int k = 0; k < 16; k++) {
            ulonglong2 xv = xr[k];
            z2[2 * k]     = fma2(p2, xv.x, z2[2 * k]);
            z2[2 * k + 1] = fma2(p2, xv.y, z2[2 * k + 1]);
        }
    }

    // Park z in smem (x tile is dead) so phase 5 can walk it scalar-wise
    // without dynamic register-array indexing.
    __syncwarp();
    {
        ulonglong2* zrow = (ulonglong2*)(xs + lane * XS);
#pragma unroll
        for (int k = 0; k < 16; k++) {
            ulonglong2 v;
            v.x = z2[2 * k];
            v.y = z2[2 * k + 1];
            zrow[k] = v;
        }
    }
    __syncwarp();

    // ---- Phase 5: o_t = z_t @ Wv  (same structure as phase 1) ----
    u64 o2[32];
#pragma unroll
    for (int k = 0; k < 32; k++) o2[k] = 0ULL;
    {
        const float4* zrow4 = (const float4*)(xs + lane * XS);
#pragma unroll 1
        for (int dc = 0; dc < 16; dc++) {
            float4 zv4 = zrow4[dc];
#pragma unroll
            for (int j = 0; j < 4; j++) {
                float zv = (j == 0) ? zv4.x : (j == 1) ? zv4.y : (j == 2) ? zv4.z : zv4.w;
                u64 zd = pack2(zv, zv);
                const ulonglong2* Wr = (const ulonglong2*)(Wvs + ((4 * dc + j) << 6));
#pragma unroll
                for (int k = 0; k < 16; k++) {
                    ulonglong2 wv = Wr[k];
                    o2[2 * k]     = fma2(zd, wv.x, o2[2 * k]);
                    o2[2 * k + 1] = fma2(zd, wv.y, o2[2 * k + 1]);
                }
            }
        }
    }

    // Stage o rows in smem, then fully-coalesced global store.
    __syncwarp();
    {
        ulonglong2* orow = (ulonglong2*)(xs + lane * XS);
#pragma unroll
        for (int k = 0; k < 16; k++) {
            ulonglong2 v;
            v.x = o2[2 * k];
            v.y = o2[2 * k + 1];
            orow[k] = v;
        }
    }
    __syncwarp();
    for (int i = lane; i < (T * H) / 4; i += 32) {
        int r = i >> 4;
        int c = (i & 15) << 2;
        ((float4*)ob)[i] = *(const float4*)(xs + r * XS + c);
    }
}

// ---------------------------------------------------------------------------
extern "C" void kernel_launch(void* const* d_in, const int* in_sizes, int n_in,
                              void* d_out, int out_size) {
    const float* x  = (const float*)d_in[0];
    const float* Wk = (const float*)d_in[1];
    const float* Wq = (const float*)d_in[2];
    const float* Wv = (const float*)d_in[3];
    float* out = (float*)d_out;

    int nbatch = in_sizes[0] / (T * D);

    size_t smem = (size_t)(2 * D * H + WARPS_PER_CTA * T * XS) * sizeof(float);
    cudaFuncSetAttribute(head_kernel,
                         cudaFuncAttributeMaxDynamicSharedMemorySize, (int)smem);

    compute_M_kernel<<<1, 256>>>(Wk, Wq);
    int grid = (nbatch + WARPS_PER_CTA - 1) / WARPS_PER_CTA;
    head_kernel<<<grid, THREADS, smem>>>(x, Wv, out, nbatch);
}

// round 4
// speedup vs baseline: 1.1893x; 1.1893x over previous
#include <cuda_runtime.h>

// Fused causal single-head attention, fp32.  B=16384, T=32, D=64, H=64.
//   out = softmax_causal( x (8 Wq Wk^T) x^T ) @ x @ Wv
// Register-blocked warp-GEMM: one warp per batch; every GEMM phase is an
// outer-product over k with an 8x8 (or 8x4) per-lane fp32 accumulator tile in
// registers; all shared-memory operand loads are conflict-free scalar LDS.32.
// This cuts L1tex wavefronts ~3.5x vs the broadcast-LDS formulation (the
// measured bottleneck in round 3: L1=87.3%, fma=39.7%).

constexpr int T = 32;     // context
constexpr int D = 64;     // ndim
constexpr int H = 64;     // head size
constexpr int XRS = 65;   // x row-major stride (floats): bank = (r + c) mod 32
constexpr int YCS = 33;   // column-major stride for yc/pT/zc: bank = (col + row) mod 32
constexpr int WARPS_PER_CTA = 4;
constexpr int THREADS = 128;
constexpr int PER_WARP = T * XRS + D * YCS;   // 2080 + 2112 floats

__device__ float g_M[D * D];   // M = 8 * Wq * Wk^T

typedef unsigned long long u64;

__device__ __forceinline__ u64 fma2(u64 a, u64 b, u64 c) {
    u64 d;
    asm("fma.rn.f32x2 %0, %1, %2, %3;" : "=l"(d) : "l"(a), "l"(b), "l"(c));
    return d;
}
__device__ __forceinline__ u64 pack2(float lo, float hi) {
    u64 r;
    asm("mov.b64 %0, {%1, %2};" : "=l"(r) : "f"(lo), "f"(hi));
    return r;
}
__device__ __forceinline__ float2 unpack2(u64 v) {
    float2 f;
    asm("mov.b64 {%0, %1}, %2;" : "=f"(f.x), "=f"(f.y) : "l"(v));
    return f;
}

// ---------------------------------------------------------------------------
// Pre-kernel: M[i][j] = 8 * sum_h Wq[i][h] * Wk[j][h]
// ---------------------------------------------------------------------------
__global__ void compute_M_kernel(const float* __restrict__ Wk,
                                 const float* __restrict__ Wq) {
    __shared__ float sq[D * H];
    __shared__ float sk[D * H];
    int tid = threadIdx.x;
    for (int i = tid; i < (D * H) / 4; i += blockDim.x) {
        ((float4*)sq)[i] = ((const float4*)Wq)[i];
        ((float4*)sk)[i] = ((const float4*)Wk)[i];
    }
    __syncthreads();
    for (int e = tid; e < D * D; e += blockDim.x) {
        int i = e >> 6;
        int j = e & 63;
        float acc = 0.f;
#pragma unroll
        for (int h = 0; h < H; h++) acc += sq[i * H + h] * sk[j * H + h];
        g_M[e] = 8.0f * acc;
    }
}

// ---------------------------------------------------------------------------
// Main kernel. Lane decomposition: rg = lane>>3 (4 row groups of 8 rows),
// cg = lane&7 (8 col groups; columns cg+8j). 32x64 GEMM tiles: 8 rows x 8 cols
// per lane (32 u64 accums). 32x32 S tile: 8 rows x 4 cols (16 u64).
// ---------------------------------------------------------------------------
__global__ void __launch_bounds__(THREADS, 2)
head_kernel(const float* __restrict__ x,
            const float* __restrict__ Wv,
            float* __restrict__ out,
            int nbatch) {
    extern __shared__ float sm[];
    float* Ms  = sm;            // D*D
    float* Wvs = sm + D * D;    // D*H
    const int tid  = threadIdx.x;
    const int warp = tid >> 5;
    const int lane = tid & 31;
    const int rg = lane >> 3;         // 0..3
    const int cg = lane & 7;          // 0..7
    const int r0 = rg << 3;           // first row of this lane's row group

    float* xr = sm + 2 * D * H + warp * PER_WARP;   // [T][XRS] row-major x
    float* yc = xr + T * XRS;                        // [D][YCS] col-major scratch

    const int batch = blockIdx.x * WARPS_PER_CTA + warp;
    const bool active = (batch < nbatch);

    // ---- Stage x: coalesced LDG.128, scalar STS (2-way conflict, cheap) ----
    if (active) {
        const float4* xg4 = (const float4*)(x + (size_t)batch * (T * D));
        for (int i = lane; i < (T * D) / 4; i += 32) {
            float4 v = xg4[i];
            int t = i >> 4;
            int c = (i & 15) << 2;
            float* p = xr + t * XRS + c;
            p[0] = v.x; p[1] = v.y; p[2] = v.z; p[3] = v.w;
        }
    }
    // Cooperative weight load
    for (int i = tid; i < (D * D) / 4; i += THREADS)
        ((float4*)Ms)[i] = ((const float4*)g_M)[i];
    for (int i = tid; i < (D * H) / 4; i += THREADS)
        ((float4*)Wvs)[i] = ((const float4*)Wv)[i];
    __syncthreads();

    if (!active) return;

    u64 acc[32];

    // ================= Phase A: y = x @ M  (32x64, k = d over 64) ==========
#pragma unroll
    for (int q = 0; q < 32; q++) acc[q] = 0ULL;
#pragma unroll 4
    for (int k = 0; k < D; k++) {
        float a[8], b[8];
#pragma unroll
        for (int i = 0; i < 8; i++) a[i] = xr[(r0 + i) * XRS + k];   // x[:,k]
#pragma unroll
        for (int j = 0; j < 8; j++) b[j] = Ms[k * 64 + cg + 8 * j];  // M[k,:]
        u64 b2[4];
#pragma unroll
        for (int jj = 0; jj < 4; jj++) b2[jj] = pack2(b[2 * jj], b[2 * jj + 1]);
#pragma unroll
        for (int i = 0; i < 8; i++) {
            u64 a2 = pack2(a[i], a[i]);
#pragma unroll
            for (int jj = 0; jj < 4; jj++)
                acc[i * 4 + jj] = fma2(a2, b2[jj], acc[i * 4 + jj]);
        }
    }
    __syncwarp();
    // store y column-major: yc[col][row]; lane cols = cg+16jj (lo), cg+16jj+8 (hi)
#pragma unroll
    for (int i = 0; i < 8; i++)
#pragma unroll
        for (int jj = 0; jj < 4; jj++) {
            float2 f = unpack2(acc[i * 4 + jj]);
            yc[(cg + 16 * jj) * YCS + r0 + i]     = f.x;
            yc[(cg + 16 * jj + 8) * YCS + r0 + i] = f.y;
        }
    __syncwarp();

    // ================= Phase S: S = y @ x^T (32x32, k = h over 64) =========
    // lane tile: rows r0..r0+7, cols {cg, cg+8, cg+16, cg+24}
    u64 accS[16];
#pragma unroll
    for (int q = 0; q < 16; q++) accS[q] = 0ULL;
#pragma unroll 4
    for (int k = 0; k < H; k++) {
        float a[8], bs[4];
#pragma unroll
        for (int i = 0; i < 8; i++) a[i] = yc[k * YCS + r0 + i];       // y[:,k]
#pragma unroll
        for (int j = 0; j < 4; j++) bs[j] = xr[(cg + 8 * j) * XRS + k]; // x[s][k]
        u64 b2[2];
        b2[0] = pack2(bs[0], bs[1]);   // cols cg, cg+8
        b2[1] = pack2(bs[2], bs[3]);   // cols cg+16, cg+24
#pragma unroll
        for (int i = 0; i < 8; i++) {
            u64 a2 = pack2(a[i], a[i]);
            accS[i * 2 + 0] = fma2(a2, b2[0], accS[i * 2 + 0]);
            accS[i * 2 + 1] = fma2(a2, b2[1], accS[i * 2 + 1]);
        }
    }
    __syncwarp();

    // ================= Softmax (causal), p stored as pT[s][t] ==============
    float* pT = yc;   // overlay: y columns are dead
#pragma unroll
    for (int i = 0; i < 8; i++) {
        int t = r0 + i;
        float2 g0 = unpack2(accS[i * 2]);
        float2 g1 = unpack2(accS[i * 2 + 1]);
        float v0 = (cg      <= t) ? g0.x : -1e30f;
        float v1 = (cg + 8  <= t) ? g0.y : -1e30f;
        float v2 = (cg + 16 <= t) ? g1.x : -1e30f;
        float v3 = (cg + 24 <= t) ? g1.y : -1e30f;
        float m = fmaxf(fmaxf(v0, v1), fmaxf(v2, v3));
        m = fmaxf(m, __shfl_xor_sync(0xffffffffu, m, 1));
        m = fmaxf(m, __shfl_xor_sync(0xffffffffu, m, 2));
        m = fmaxf(m, __shfl_xor_sync(0xffffffffu, m, 4));
        float e0 = __expf(v0 - m);
        float e1 = __expf(v1 - m);
        float e2 = __expf(v2 - m);
        float e3 = __expf(v3 - m);
        float s = (e0 + e1) + (e2 + e3);
        s += __shfl_xor_sync(0xffffffffu, s, 1);
        s += __shfl_xor_sync(0xffffffffu, s, 2);
        s += __shfl_xor_sync(0xffffffffu, s, 4);
        float inv = 1.0f / s;
        pT[cg * YCS + t]        = e0 * inv;
        pT[(cg + 8) * YCS + t]  = e1 * inv;
        pT[(cg + 16) * YCS + t] = e2 * inv;
        pT[(cg + 24) * YCS + t] = e3 * inv;
    }
    __syncwarp();

    // ================= Phase Z: z = p @ x  (32x64, k = s over 32) ==========
#pragma unroll
    for (int q = 0; q < 32; q++) acc[q] = 0ULL;
#pragma unroll 4
    for (int s = 0; s < T; s++) {
        float a[8], b[8];
#pragma unroll
        for (int i = 0; i < 8; i++) a[i] = pT[s * YCS + r0 + i];      // p[:,s]
#pragma unroll
        for (int j = 0; j < 8; j++) b[j] = xr[s * XRS + cg + 8 * j];  // x[s,:]
        u64 b2[4];
#pragma unroll
        for (int jj = 0; jj < 4; jj++) b2[jj] = pack2(b[2 * jj], b[2 * jj + 1]);
#pragma unroll
        for (int i = 0; i < 8; i++) {
            u64 a2 = pack2(a[i], a[i]);
#pragma unroll
            for (int jj = 0; jj < 4; jj++)
                acc[i * 4 + jj] = fma2(a2, b2[jj], acc[i * 4 + jj]);
        }
    }
    __syncwarp();
    // store z column-major (overlay: pT dead)
    float* zc = yc;
#pragma unroll
    for (int i = 0; i < 8; i++)
#pragma unroll
        for (int jj = 0; jj < 4; jj++) {
            float2 f = unpack2(acc[i * 4 + jj]);
            zc[(cg + 16 * jj) * YCS + r0 + i]     = f.x;
            zc[(cg + 16 * jj + 8) * YCS + r0 + i] = f.y;
        }
    __syncwarp();

    // ================= Phase O: o = z @ Wv (32x64, k = d over 64) ==========
#pragma unroll
    for (int q = 0; q < 32; q++) acc[q] = 0ULL;
#pragma unroll 4
    for (int k = 0; k < D; k++) {
        float a[8], b[8];
#pragma unroll
        for (int i = 0; i < 8; i++) a[i] = zc[k * YCS + r0 + i];       // z[:,k]
#pragma unroll
        for (int j = 0; j < 8; j++) b[j] = Wvs[k * 64 + cg + 8 * j];   // Wv[k,:]
        u64 b2[4];
#pragma unroll
        for (int jj = 0; jj < 4; jj++) b2[jj] = pack2(b[2 * jj], b[2 * jj + 1]);
#pragma unroll
        for (int i = 0; i < 8; i++) {
            u64 a2 = pack2(a[i], a[i]);
#pragma unroll
            for (int jj = 0; jj < 4; jj++)
                acc[i * 4 + jj] = fma2(a2, b2[jj], acc[i * 4 + jj]);
        }
    }
    __syncwarp();

    // ---- stage o row-major into xr (dead), then coalesced STG.128 ----
#pragma unroll
    for (int i = 0; i < 8; i++)
#pragma unroll
        for (int jj = 0; jj < 4; jj++) {
            float2 f = unpack2(acc[i * 4 + jj]);
            xr[(r0 + i) * XRS + cg + 16 * jj]     = f.x;
            xr[(r0 + i) * XRS + cg + 16 * jj + 8] = f.y;
        }
    __syncwarp();
    {
        float4* ob4 = (float4*)(out + (size_t)batch * (T * H));
        for (int i = lane; i < (T * H) / 4; i += 32) {
            int t = i >> 4;
            int c = (i & 15) << 2;
            const float* p = xr + t * XRS + c;
            float4 v;
            v.x = p[0]; v.y = p[1]; v.z = p[2]; v.w = p[3];
            ob4[i] = v;
        }
    }
}

// ---------------------------------------------------------------------------
extern "C" void kernel_launch(void* const* d_in, const int* in_sizes, int n_in,
                              void* d_out, int out_size) {
    const float* x  = (const float*)d_in[0];
    const float* Wk = (const float*)d_in[1];
    const float* Wq = (const float*)d_in[2];
    const float* Wv = (const float*)d_in[3];
    float* out = (float*)d_out;

    int nbatch = in_sizes[0] / (T * D);

    size_t smem = (size_t)(2 * D * H + WARPS_PER_CTA * PER_WARP) * sizeof(float);
    cudaFuncSetAttribute(head_kernel,
                         cudaFuncAttributeMaxDynamicSharedMemorySize, (int)smem);

    compute_M_kernel<<<1, 256>>>(Wk, Wq);
    int grid = (nbatch + WARPS_PER_CTA - 1) / WARPS_PER_CTA;
    head_kernel<<<grid, THREADS, smem>>>(x, Wv, out, nbatch);
}